// round 1
// baseline (speedup 1.0000x reference)
#include <cuda_runtime.h>
#include <math.h>

// Problem constants
#define Bv 2
#define Sv 1024
#define Dv 768
#define Hv 12
#define Lv 12
#define Vv 50257
#define DHv 64
#define HIDv 9216
#define Mv (Bv*Sv)          // 2048 token rows

// ------------------- scratch (device globals; no runtime alloc) -------------------
__device__ float g_x  [Mv*Dv];        // running residual stream
__device__ float g_n1 [Mv*Dv];        // ln1 output
__device__ float g_qkv[Mv*3*Dv];      // qkv projection
__device__ float g_val[Mv*Dv];        // attention output (pre-proj)
__device__ float g_att[Mv*Dv];        // after Wo + residual
__device__ float g_n2 [Mv*Dv];        // ln2 output
__device__ float g_ffn[Mv*HIDv];      // ffn hidden

// ------------------------------- embedding -------------------------------
__global__ void embed_kernel(const int* __restrict__ vocab,
                             const int* __restrict__ pos,
                             const float* __restrict__ vW,
                             const float* __restrict__ pW) {
    int row = blockIdx.x;                    // 0..2047
    int v = vocab[row];
    int p = pos[row];
    const float* vr = vW + (long)v * Dv;
    const float* pr = pW + (long)p * Dv;
    float* o = g_x + (long)row * Dv;
    for (int d = threadIdx.x; d < Dv; d += blockDim.x)
        o[d] = vr[d] + pr[d];
}

// ------------------------------- layernorm -------------------------------
__global__ void __launch_bounds__(256) ln_kernel(const float* __restrict__ in,
                                                 const float* __restrict__ s,
                                                 const float* __restrict__ b,
                                                 float* __restrict__ out) {
    int row = blockIdx.x;
    const float* x = in + (long)row * Dv;
    __shared__ float red[256];
    int tid = threadIdx.x;

    float sum = 0.f;
    for (int d = tid; d < Dv; d += 256) sum += x[d];
    red[tid] = sum; __syncthreads();
    #pragma unroll
    for (int o = 128; o > 0; o >>= 1) {
        if (tid < o) red[tid] += red[tid + o];
        __syncthreads();
    }
    float mean = red[0] * (1.0f / Dv);
    __syncthreads();

    float vs = 0.f;
    for (int d = tid; d < Dv; d += 256) { float t = x[d] - mean; vs += t * t; }
    red[tid] = vs; __syncthreads();
    #pragma unroll
    for (int o = 128; o > 0; o >>= 1) {
        if (tid < o) red[tid] += red[tid + o];
        __syncthreads();
    }
    float rstd = rsqrtf(red[0] * (1.0f / Dv) + 1e-5f);

    float* orow = out + (long)row * Dv;
    for (int d = tid; d < Dv; d += 256)
        orow[d] = (x[d] - mean) * rstd * s[d] + b[d];
}

// ------------------------------- SGEMM -------------------------------
// C[M,N] = A[M,K] @ B[K,N]  (+bias[n]) (leaky-relu) (+res[m,n])
// BM=BN=128, BK=8, 256 threads, 8x8 per thread. M must be multiple of 128.
template<int BIAS, int RELU, int RES>
__global__ void __launch_bounds__(256) gemm_kernel(
    const float* __restrict__ A, const float* __restrict__ Bm,
    const float* __restrict__ bias, const float* __restrict__ res,
    float* __restrict__ C, int M, int N, int K)
{
    const int BM = 128, BN = 128, BK = 8, TM = 8, TN = 8;
    __shared__ float As[BK][BM];
    __shared__ float Bs[BK][BN + 4];

    int tid = threadIdx.x;
    int n0 = blockIdx.x * BN;
    int m0 = blockIdx.y * BM;

    // A-tile load mapping: each thread loads float4 of A (row a_row, cols a_col..+3)
    int a_row = tid >> 1;
    int a_col = (tid & 1) * 4;
    // B-tile load mapping: row b_row, cols b_col..+3
    int b_row = tid >> 5;
    int b_col = (tid & 31) * 4;

    int tx = tid & 15;       // 0..15 -> n
    int ty = tid >> 4;       // 0..15 -> m

    float acc[TM][TN];
    #pragma unroll
    for (int i = 0; i < TM; i++)
        #pragma unroll
        for (int j = 0; j < TN; j++) acc[i][j] = 0.f;

    for (int k0 = 0; k0 < K; k0 += BK) {
        // load A (K divisible by 8; aligned -> float4 ok)
        const float4 a4 = *(const float4*)(A + (long)(m0 + a_row) * K + k0 + a_col);
        As[a_col + 0][a_row] = a4.x;
        As[a_col + 1][a_row] = a4.y;
        As[a_col + 2][a_row] = a4.z;
        As[a_col + 3][a_row] = a4.w;
        // load B (N may be ragged; scalar guarded loads)
        const float* Bp = Bm + (long)(k0 + b_row) * N + n0 + b_col;
        #pragma unroll
        for (int i = 0; i < 4; i++)
            Bs[b_row][b_col + i] = (n0 + b_col + i < N) ? Bp[i] : 0.f;
        __syncthreads();

        #pragma unroll
        for (int kk = 0; kk < BK; kk++) {
            float af[TM], bf[TN];
            #pragma unroll
            for (int i = 0; i < TM; i++) af[i] = As[kk][ty * TM + i];
            #pragma unroll
            for (int j = 0; j < TN; j++) bf[j] = Bs[kk][tx * TN + j];
            #pragma unroll
            for (int i = 0; i < TM; i++)
                #pragma unroll
                for (int j = 0; j < TN; j++)
                    acc[i][j] = fmaf(af[i], bf[j], acc[i][j]);
        }
        __syncthreads();
    }

    #pragma unroll
    for (int i = 0; i < TM; i++) {
        int m = m0 + ty * TM + i;
        #pragma unroll
        for (int j = 0; j < TN; j++) {
            int n = n0 + tx * TN + j;
            if (n < N) {
                float v = acc[i][j];
                if (BIAS) v += bias[n];
                if (RELU) v = (v > 0.f) ? v : 0.01f * v;
                if (RES)  v += res[(long)m * N + n];
                C[(long)m * N + n] = v;
            }
        }
    }
}

// ------------------------------- fused attention -------------------------------
// One thread per query row; 128 queries per block; keys streamed in 64-key
// smem chunks with online softmax. Masked logits == -1e5 (exp underflows to 0,
// matching the reference's multiplicative-mask trick exactly).
__global__ void __launch_bounds__(128) attn_kernel() {
    int bh = blockIdx.x;           // b*H + h
    int b  = bh / Hv;
    int h  = bh % Hv;
    int qt = blockIdx.y;           // query tile (128 queries)
    int tid = threadIdx.x;
    int qi = qt * 128 + tid;

    const float* qrow = g_qkv + (long)(b * Sv + qi) * (3 * Dv) + h * 3 * DHv;
    float q[DHv];
    #pragma unroll
    for (int d = 0; d < DHv; d++) q[d] = qrow[d];

    float o[DHv];
    #pragma unroll
    for (int d = 0; d < DHv; d++) o[d] = 0.f;
    float mx = -1e30f, l = 0.f;

    __shared__ float Ks[64][DHv];
    __shared__ float Vs[64][DHv];

    int kend = qt * 128 + 128;     // max key (exclusive) needed by this block

    for (int ks0 = 0; ks0 < kend; ks0 += 64) {
        // cooperative load of 64 keys + values (float4 per thread iter)
        for (int idx = tid; idx < 64 * 16; idx += 128) {
            int j  = idx >> 4;             // key within chunk
            int dc = (idx & 15) * 4;       // dim offset
            const float* kr = g_qkv + (long)(b * Sv + ks0 + j) * (3 * Dv)
                              + h * 3 * DHv + DHv + dc;
            *(float4*)&Ks[j][dc] = *(const float4*)kr;
            *(float4*)&Vs[j][dc] = *(const float4*)(kr + DHv);
        }
        __syncthreads();

        #pragma unroll 1
        for (int sub = 0; sub < 64; sub += 16) {
            float s[16];
            #pragma unroll
            for (int jj = 0; jj < 16; jj++) {
                float acc = 0.f;
                #pragma unroll
                for (int d = 0; d < DHv; d++)
                    acc = fmaf(q[d], Ks[sub + jj][d], acc);
                int kj = ks0 + sub + jj;
                s[jj] = (kj <= qi) ? acc * 0.125f : -1e5f;
            }
            float cm = s[0];
            #pragma unroll
            for (int jj = 1; jj < 16; jj++) cm = fmaxf(cm, s[jj]);
            float mnew = fmaxf(mx, cm);
            float scale = __expf(mx - mnew);
            l *= scale;
            #pragma unroll
            for (int d = 0; d < DHv; d++) o[d] *= scale;
            #pragma unroll
            for (int jj = 0; jj < 16; jj++) {
                float p = __expf(s[jj] - mnew);
                l += p;
                #pragma unroll
                for (int d = 0; d < DHv; d++)
                    o[d] = fmaf(p, Vs[sub + jj][d], o[d]);
            }
            mx = mnew;
        }
        __syncthreads();
    }

    float inv = 1.0f / l;
    float* outp = g_val + (long)(b * Sv + qi) * Dv + h * DHv;
    #pragma unroll
    for (int d = 0; d < DHv; d++) outp[d] = o[d] * inv;
}

// ------------------------------- driver -------------------------------
extern "C" void kernel_launch(void* const* d_in, const int* in_sizes, int n_in,
                              void* d_out, int out_size) {
    (void)in_sizes; (void)n_in; (void)out_size;
    const int*   vocab = (const int*)  d_in[0];
    const int*   pos   = (const int*)  d_in[1];
    const float* vW    = (const float*)d_in[2];
    const float* pW    = (const float*)d_in[3];
    const float* ln1_s = (const float*)d_in[4];
    const float* ln1_b = (const float*)d_in[5];
    const float* Wqkv  = (const float*)d_in[6];
    const float* bqkv  = (const float*)d_in[7];
    const float* Wo    = (const float*)d_in[8];
    const float* bo    = (const float*)d_in[9];
    const float* ln2_s = (const float*)d_in[10];
    const float* ln2_b = (const float*)d_in[11];
    const float* W1    = (const float*)d_in[12];
    const float* b1    = (const float*)d_in[13];
    const float* W2    = (const float*)d_in[14];
    const float* b2    = (const float*)d_in[15];
    const float* outW  = (const float*)d_in[16];
    float* out = (float*)d_out;

    // resolve device-global scratch addresses (host-side lookups; capture-safe)
    float *p_x, *p_n1, *p_qkv, *p_val, *p_att, *p_n2, *p_ffn;
    cudaGetSymbolAddress((void**)&p_x,   g_x);
    cudaGetSymbolAddress((void**)&p_n1,  g_n1);
    cudaGetSymbolAddress((void**)&p_qkv, g_qkv);
    cudaGetSymbolAddress((void**)&p_val, g_val);
    cudaGetSymbolAddress((void**)&p_att, g_att);
    cudaGetSymbolAddress((void**)&p_n2,  g_n2);
    cudaGetSymbolAddress((void**)&p_ffn, g_ffn);

    dim3 gemm_blk(256);

    // embedding
    embed_kernel<<<Mv, 256>>>(vocab, pos, vW, pW);

    for (int l = 0; l < Lv; l++) {
        const float* l1s = ln1_s + (long)l * Dv;
        const float* l1b = ln1_b + (long)l * Dv;
        const float* wq  = Wqkv  + (long)l * Dv * 3 * Dv;
        const float* bq  = bqkv  + (long)l * 3 * Dv;
        const float* wo  = Wo    + (long)l * Dv * Dv;
        const float* bo_ = bo    + (long)l * Dv;
        const float* l2s = ln2_s + (long)l * Dv;
        const float* l2b = ln2_b + (long)l * Dv;
        const float* w1  = W1    + (long)l * Dv * HIDv;
        const float* bb1 = b1    + (long)l * HIDv;
        const float* w2  = W2    + (long)l * HIDv * Dv;
        const float* bb2 = b2    + (long)l * Dv;

        // ln1
        ln_kernel<<<Mv, 256>>>(p_x, l1s, l1b, p_n1);
        // qkv = n1 @ Wqkv + bqkv        [2048, 2304]
        gemm_kernel<1,0,0><<<dim3((3*Dv+127)/128, Mv/128), gemm_blk>>>(
            p_n1, wq, bq, nullptr, p_qkv, Mv, 3*Dv, Dv);
        // attention -> g_val
        attn_kernel<<<dim3(Bv*Hv, Sv/128), 128>>>();
        // att = val @ Wo + bo + x       [2048, 768]
        gemm_kernel<1,0,1><<<dim3(Dv/128, Mv/128), gemm_blk>>>(
            p_val, wo, bo_, p_x, p_att, Mv, Dv, Dv);
        // ln2
        ln_kernel<<<Mv, 256>>>(p_att, l2s, l2b, p_n2);
        // ffn hidden = leaky_relu(n2 @ W1 + b1)   [2048, 9216]
        gemm_kernel<1,1,0><<<dim3(HIDv/128, Mv/128), gemm_blk>>>(
            p_n2, w1, bb1, nullptr, p_ffn, Mv, HIDv, Dv);
        // x = ffn @ W2 + b2 + n2        [2048, 768]   (residual is n2!)
        gemm_kernel<1,0,1><<<dim3(Dv/128, Mv/128), gemm_blk>>>(
            p_ffn, w2, bb2, p_n2, p_x, Mv, Dv, HIDv);
    }

    // logits = x @ out_W               [2048, 50257]
    gemm_kernel<0,0,0><<<dim3((Vv+127)/128, Mv/128), gemm_blk>>>(
        p_x, outW, nullptr, nullptr, out, Mv, Vv, Dv);
}